// round 6
// baseline (speedup 1.0000x reference)
#include <cuda_runtime.h>
#include <cuda_fp16.h>
#include <cstdint>

#define TT 16384
#define DD 768
#define HH 3072
#define EE 8
#define HPAD (TT + 128)

// ---------------- scratch globals ------------------------------------------
__device__ int   g_cnt[EE];
__device__ int   g_tok[EE * TT];
__device__ float g_wt [EE * TT];
__device__ int   g_kidx[EE * TT];
__device__ __half g_x16[(size_t)TT * DD];
__device__ __half g_w1t[(size_t)EE * HH * DD];  // [E][H][D] K-major
__device__ __half g_w2t[(size_t)EE * DD * HH];  // [E][D][H] K-major
__device__ __half g_h16[(size_t)EE * HPAD * HH];
__device__ float g_yp[(size_t)TT * 2 * DD];

// ---------------- PTX helpers (base ISA only) -------------------------------
__device__ __forceinline__ uint32_t smem_u32(const void* p) {
    uint32_t a;
    asm("{ .reg .u64 t; cvta.to.shared.u64 t, %1; cvt.u32.u64 %0, t; }"
        : "=r"(a) : "l"(p));
    return a;
}
__device__ __forceinline__ void cpa16(uint32_t dst, const void* src) {
    asm volatile("cp.async.cg.shared.global [%0], [%1], 16;" :: "r"(dst), "l"(src));
}
__device__ __forceinline__ void cpa_commit() {
    asm volatile("cp.async.commit_group;" ::: "memory");
}
template<int N> __device__ __forceinline__ void cpa_wait() {
    asm volatile("cp.async.wait_group %0;" :: "n"(N) : "memory");
}
__device__ __forceinline__ void ldsm4(uint32_t* r, uint32_t addr) {
    asm volatile("ldmatrix.sync.aligned.m8n8.x4.shared.b16 {%0,%1,%2,%3}, [%4];"
                 : "=r"(r[0]), "=r"(r[1]), "=r"(r[2]), "=r"(r[3]) : "r"(addr));
}
__device__ __forceinline__ void mma16816(float* c, const uint32_t* a, const uint32_t* b) {
    asm volatile(
        "mma.sync.aligned.m16n8k16.row.col.f32.f16.f16.f32 "
        "{%0,%1,%2,%3}, {%4,%5,%6,%7}, {%8,%9}, {%0,%1,%2,%3};"
        : "+f"(c[0]), "+f"(c[1]), "+f"(c[2]), "+f"(c[3])
        : "r"(a[0]), "r"(a[1]), "r"(a[2]), "r"(a[3]), "r"(b[0]), "r"(b[1]));
}
__device__ __forceinline__ uint32_t swz(uint32_t off) {
    return off ^ ((off >> 3) & 0x70);
}
__device__ __forceinline__ float gelu_exact(float v) {
    return 0.5f * v * (1.f + erff(v * 0.70710678118654752440f));
}

// ---------------- small kernels --------------------------------------------
__global__ void zero_cnt_kernel() {
    if (threadIdx.x < EE) g_cnt[threadIdx.x] = 0;
}

__global__ __launch_bounds__(256) void convert_x_kernel(const float* __restrict__ x) {
    size_t i = ((size_t)blockIdx.x * 256 + threadIdx.x) * 4;
    float4 v = *(const float4*)(x + i);
    __half2 p0 = __floats2half2_rn(v.x, v.y);
    __half2 p1 = __floats2half2_rn(v.z, v.w);
    uint2 o; o.x = *(uint32_t*)&p0; o.y = *(uint32_t*)&p1;
    *(uint2*)(g_x16 + i) = o;
}

// which=0: w1 [E][D][H] -> [E][H][D]; which=1: w2 [E][H][D] -> [E][D][H]
__global__ __launch_bounds__(256) void transpose_split_kernel(
    const float* __restrict__ in, int which)
{
    int R = which ? HH : DD;
    int C = which ? DD : HH;
    __half* outp = which ? g_w2t : g_w1t;
    __shared__ float tile[32][33];
    int e  = blockIdx.z;
    int r0 = blockIdx.y * 32, c0 = blockIdx.x * 32;
    const float* src = in + (size_t)e * R * C;
    for (int i = threadIdx.y; i < 32; i += 8)
        tile[i][threadIdx.x] = src[(size_t)(r0 + i) * C + c0 + threadIdx.x];
    __syncthreads();
    __half* dst = outp + (size_t)e * R * C;
    for (int i = threadIdx.y; i < 32; i += 8) {
        float v = tile[threadIdx.x][i];
        dst[(size_t)(c0 + i) * R + r0 + threadIdx.x] = __float2half_rn(v);
    }
}

__global__ __launch_bounds__(256) void router_kernel(
    const float* __restrict__ x,
    const float* __restrict__ rw,
    const float* __restrict__ rb)
{
    int gwarp = (blockIdx.x * blockDim.x + threadIdx.x) >> 5;
    int lane  = threadIdx.x & 31;
    if (gwarp >= TT) return;
    const float* xr = x + (size_t)gwarp * DD;

    float acc[EE];
#pragma unroll
    for (int e = 0; e < EE; e++) acc[e] = 0.f;
    for (int d = lane; d < DD; d += 32) {
        float xv = xr[d];
        const float4 w0 = *(const float4*)(rw + (size_t)d * EE);
        const float4 w1 = *(const float4*)(rw + (size_t)d * EE + 4);
        acc[0] += xv * w0.x; acc[1] += xv * w0.y;
        acc[2] += xv * w0.z; acc[3] += xv * w0.w;
        acc[4] += xv * w1.x; acc[5] += xv * w1.y;
        acc[6] += xv * w1.z; acc[7] += xv * w1.w;
    }
#pragma unroll
    for (int off = 16; off; off >>= 1)
#pragma unroll
        for (int e = 0; e < EE; e++)
            acc[e] += __shfl_down_sync(0xffffffffu, acc[e], off);
    if (lane == 0) {
        float lg[EE];
#pragma unroll
        for (int e = 0; e < EE; e++) lg[e] = acc[e] + rb[e];
        int i0 = 0; float v0 = lg[0];
#pragma unroll
        for (int e = 1; e < EE; e++) if (lg[e] > v0) { v0 = lg[e]; i0 = e; }
        int i1 = -1; float v1 = -3.4e38f;
#pragma unroll
        for (int e = 0; e < EE; e++) {
            if (e == i0) continue;
            if (lg[e] > v1) { v1 = lg[e]; i1 = e; }
        }
        float e1 = __expf(v1 - v0);
        float w0 = 1.f / (1.f + e1);
        float w1 = e1 * w0;
        int s0 = atomicAdd(&g_cnt[i0], 1);
        g_tok[i0 * TT + s0] = gwarp; g_wt[i0 * TT + s0] = w0; g_kidx[i0 * TT + s0] = 0;
        int s1 = atomicAdd(&g_cnt[i1], 1);
        g_tok[i1 * TT + s1] = gwarp; g_wt[i1 * TT + s1] = w1; g_kidx[i1 * TT + s1] = 1;
    }
}

// ---------------- fp16 GEMM via mma.sync (tensor pipe) ----------------------
// D[m,n] = sum_k A[m,k]*B[n,k]. CTA: 128m x 256n, 8 warps (2m x 4n),
// warp tile 64x64. K-chunk 64, SW128 K-major smem, 4-stage cp.async,
// single __syncthreads per chunk.
template<int K_TOT, bool G1>
__global__ void __launch_bounds__(256, 1) gemm_tc_kernel(const float* __restrict__ bias)
{
    constexpr int NK    = K_TOT / 64;
    constexpr int AB    = 128 * 128;           // A bytes/stage (16 KB)
    constexpr int BB    = 256 * 128;           // B bytes/stage (32 KB)
    constexpr int STAGE = AB + BB;             // 48 KB
    constexpr int NTOT  = G1 ? HH : DD;

    int e   = blockIdx.z;
    int cnt = g_cnt[e];
    int m0  = blockIdx.y * 128;
    if (m0 >= cnt) return;
    int n0  = blockIdx.x * 256;

    extern __shared__ char dynsm[];
    uint32_t dsm = (smem_u32(dynsm) + 1023u) & ~1023u;

    int tid = threadIdx.x, wid = tid >> 5, lane = tid & 31;
    int warp_m = (wid & 1) * 64;
    int warp_n = (wid >> 1) * 64;

    // per-thread load source rows
    int lrow = tid >> 1;
    int lseg = (tid & 1) * 4;
    const __half* arow;
    {
        if (G1) {
            int gr = m0 + lrow; if (gr > cnt - 1) gr = cnt - 1;
            int t = g_tok[e * TT + gr];
            arow = g_x16 + (size_t)t * DD;
        } else {
            arow = g_h16 + ((size_t)e * HPAD + m0 + lrow) * HH;
        }
    }
    const __half* bbase = (G1 ? g_w1t : g_w2t) + (size_t)e * NTOT * (size_t)K_TOT;
    const __half* brow0 = bbase + (size_t)(n0 + lrow)       * K_TOT;
    const __half* brow1 = bbase + (size_t)(n0 + lrow + 128) * K_TOT;

    auto load_stage = [&](int s, int k0) {
        uint32_t st = dsm + s * STAGE;
#pragma unroll
        for (int q = 0; q < 4; q++) {
            int seg = lseg + q;
            uint32_t offA = swz((uint32_t)(lrow * 128 + seg * 16));
            cpa16(st + offA, arow + k0 + seg * 8);
            uint32_t offB0 = swz((uint32_t)(lrow * 128 + seg * 16));
            uint32_t offB1 = swz((uint32_t)((lrow + 128) * 128 + seg * 16));
            cpa16(st + AB + offB0, brow0 + k0 + seg * 8);
            cpa16(st + AB + offB1, brow1 + k0 + seg * 8);
        }
        cpa_commit();
    };

    float acc[4][8][4];
#pragma unroll
    for (int i = 0; i < 4; i++)
#pragma unroll
        for (int j = 0; j < 8; j++)
#pragma unroll
            for (int q = 0; q < 4; q++) acc[i][j][q] = 0.f;

    // ldmatrix per-lane address offsets (within tile, before swizzle)
    int a_r  = (lane & 7) + ((lane >> 3) & 1) * 8;
    int a_c  = (lane >> 4) * 16;
    int b_r  = (lane & 7) + (lane >> 4) * 8;
    int b_c  = ((lane >> 3) & 1) * 16;

    load_stage(0, 0);
    load_stage(1, 64);
    load_stage(2, 128);

    for (int i = 0; i < NK; i++) {
        if (i < NK - 2)       cpa_wait<2>();
        else if (i == NK - 2) cpa_wait<1>();
        else                  cpa_wait<0>();
        __syncthreads();
        if (i + 3 < NK) load_stage((i + 3) & 3, (i + 3) * 64);

        uint32_t st = dsm + (i & 3) * STAGE;
#pragma unroll
        for (int kk = 0; kk < 4; kk++) {
            int c0 = kk * 32;
            uint32_t A[4][4], B[8][2];
#pragma unroll
            for (int mf = 0; mf < 4; mf++) {
                int row = warp_m + mf * 16 + a_r;
                ldsm4(A[mf], st + swz((uint32_t)(row * 128 + c0 + a_c)));
            }
#pragma unroll
            for (int np = 0; np < 4; np++) {
                int row = warp_n + np * 16 + b_r;
                uint32_t r4[4];
                ldsm4(r4, st + AB + swz((uint32_t)(row * 128 + c0 + b_c)));
                B[2 * np][0] = r4[0]; B[2 * np][1] = r4[1];
                B[2 * np + 1][0] = r4[2]; B[2 * np + 1][1] = r4[3];
            }
#pragma unroll
            for (int mf = 0; mf < 4; mf++)
#pragma unroll
                for (int nf = 0; nf < 8; nf++)
                    mma16816(acc[mf][nf], A[mf], B[nf]);
        }
    }

    // ---------------- epilogue ----------------
    int lane4 = lane >> 2;
    int lcol  = (lane & 3) * 2;

#pragma unroll
    for (int mf = 0; mf < 4; mf++) {
#pragma unroll
        for (int h = 0; h < 2; h++) {
            int gr = m0 + warp_m + mf * 16 + h * 8 + lane4;
            if (gr >= cnt) continue;
            if (G1) {
                __half* oh = g_h16 + ((size_t)e * HPAD + gr) * HH;
                const float* bp = bias + (size_t)e * NTOT;
#pragma unroll
                for (int nf = 0; nf < 8; nf++) {
                    int n = n0 + warp_n + nf * 8 + lcol;
                    float v0 = gelu_exact(acc[mf][nf][h * 2 + 0] + bp[n]);
                    float v1 = gelu_exact(acc[mf][nf][h * 2 + 1] + bp[n + 1]);
                    __half2 hp = __floats2half2_rn(v0, v1);
                    *(uint32_t*)&oh[n] = *(uint32_t*)&hp;
                }
            } else {
                int idx = e * TT + gr;
                int   tok = g_tok[idx];
                float wt  = g_wt[idx];
                int   kx  = g_kidx[idx];
                float* orow = g_yp + ((size_t)tok * 2 + kx) * DD;
                const float* bp = bias + (size_t)e * NTOT;
#pragma unroll
                for (int nf = 0; nf < 8; nf++) {
                    int n = n0 + warp_n + nf * 8 + lcol;
                    float2 o;
                    o.x = (acc[mf][nf][h * 2 + 0] + bp[n])     * wt;
                    o.y = (acc[mf][nf][h * 2 + 1] + bp[n + 1]) * wt;
                    *(float2*)(orow + n) = o;
                }
            }
        }
    }
}

// ---------------- residual + LayerNorm --------------------------------------
__device__ __forceinline__ float block_sum256(float v) {
    __shared__ float sh[8];
    int lane = threadIdx.x & 31, w = threadIdx.x >> 5;
#pragma unroll
    for (int o = 16; o; o >>= 1) v += __shfl_down_sync(0xffffffffu, v, o);
    if (lane == 0) sh[w] = v;
    __syncthreads();
    if (threadIdx.x == 0) {
        float s = 0.f;
#pragma unroll
        for (int i = 0; i < 8; i++) s += sh[i];
        sh[0] = s;
    }
    __syncthreads();
    float r = sh[0];
    __syncthreads();
    return r;
}

__global__ __launch_bounds__(256) void ln_kernel(
    const float* __restrict__ x,
    const float* __restrict__ gamma,
    const float* __restrict__ beta,
    float* __restrict__ out)
{
    int t = blockIdx.x;
    const float* xr = x + (size_t)t * DD;
    const float* p0 = g_yp + (size_t)t * 2 * DD;
    const float* p1 = p0 + DD;

    float v[3];
    float s = 0.f;
#pragma unroll
    for (int i = 0; i < 3; i++) {
        int d = threadIdx.x + i * 256;
        v[i] = xr[d] + p0[d] + p1[d];
        s += v[i];
    }
    s = block_sum256(s);
    float mu = s * (1.f / (float)DD);
    float q = 0.f;
#pragma unroll
    for (int i = 0; i < 3; i++) { float dl = v[i] - mu; q += dl * dl; }
    q = block_sum256(q);
    float rstd = rsqrtf(q * (1.f / (float)DD) + 1e-5f);
#pragma unroll
    for (int i = 0; i < 3; i++) {
        int d = threadIdx.x + i * 256;
        out[(size_t)t * DD + d] = (v[i] - mu) * rstd * gamma[d] + beta[d];
    }
}

// ---------------------------------------------------------------------------
extern "C" void kernel_launch(void* const* d_in, const int* in_sizes, int n_in,
                              void* d_out, int out_size)
{
    (void)in_sizes; (void)n_in; (void)out_size;
    const float* x   = (const float*)d_in[0];
    const float* rw  = (const float*)d_in[1];
    const float* rb  = (const float*)d_in[2];
    const float* w1  = (const float*)d_in[3];
    const float* b1  = (const float*)d_in[4];
    const float* w2  = (const float*)d_in[5];
    const float* b2  = (const float*)d_in[6];
    const float* gam = (const float*)d_in[7];
    const float* bet = (const float*)d_in[8];
    float* out = (float*)d_out;

    const int SMEM_SZ = 4 * (128 + 256) * 128 + 1024;   // 4 stages x 48KB + pad
    cudaFuncSetAttribute(gemm_tc_kernel<DD, true>,
                         cudaFuncAttributeMaxDynamicSharedMemorySize, SMEM_SZ);
    cudaFuncSetAttribute(gemm_tc_kernel<HH, false>,
                         cudaFuncAttributeMaxDynamicSharedMemorySize, SMEM_SZ);

    zero_cnt_kernel<<<1, 32>>>();
    router_kernel<<<TT / 8, 256>>>(x, rw, rb);
    convert_x_kernel<<<(TT * DD) / (256 * 4), 256>>>(x);
    transpose_split_kernel<<<dim3(HH / 32, DD / 32, EE), dim3(32, 8)>>>(w1, 0);
    transpose_split_kernel<<<dim3(DD / 32, HH / 32, EE), dim3(32, 8)>>>(w2, 1);
    gemm_tc_kernel<DD, true><<<dim3(HH / 256, TT / 128, EE), 256, SMEM_SZ>>>(b1);
    gemm_tc_kernel<HH, false><<<dim3(DD / 256, TT / 128, EE), 256, SMEM_SZ>>>(b2);
    ln_kernel<<<TT, 256>>>(x, gam, bet, out);
}

// round 10
// speedup vs baseline: 1.1082x; 1.1082x over previous
#include <cuda_runtime.h>
#include <cuda_fp16.h>
#include <cstdint>

#define TT 16384
#define DD 768
#define HH 3072
#define EE 8
#define HPAD (TT + 128)

// ---------------- scratch globals ------------------------------------------
__device__ int   g_cnt[EE];
__device__ int   g_tok[EE * TT];
__device__ float g_wt [EE * TT];
__device__ int   g_kidx[EE * TT];
__device__ __half g_x16[(size_t)TT * DD];
__device__ __half g_w1t[(size_t)EE * HH * DD];  // [E][H][D] K-major
__device__ __half g_w2t[(size_t)EE * DD * HH];  // [E][D][H] K-major
__device__ __half g_h16[(size_t)EE * HPAD * HH];
__device__ float g_yp[(size_t)TT * 2 * DD];

// ---------------- PTX helpers (base ISA only) -------------------------------
__device__ __forceinline__ uint32_t smem_u32(const void* p) {
    uint32_t a;
    asm("{ .reg .u64 t; cvta.to.shared.u64 t, %1; cvt.u32.u64 %0, t; }"
        : "=r"(a) : "l"(p));
    return a;
}
__device__ __forceinline__ void cpa16(uint32_t dst, const void* src) {
    asm volatile("cp.async.cg.shared.global [%0], [%1], 16;" :: "r"(dst), "l"(src));
}
__device__ __forceinline__ void cpa_commit() {
    asm volatile("cp.async.commit_group;" ::: "memory");
}
template<int N> __device__ __forceinline__ void cpa_wait() {
    asm volatile("cp.async.wait_group %0;" :: "n"(N) : "memory");
}
__device__ __forceinline__ void ldsm4(uint32_t* r, uint32_t addr) {
    asm volatile("ldmatrix.sync.aligned.m8n8.x4.shared.b16 {%0,%1,%2,%3}, [%4];"
                 : "=r"(r[0]), "=r"(r[1]), "=r"(r[2]), "=r"(r[3]) : "r"(addr));
}
__device__ __forceinline__ void mma16816(float* c, const uint32_t* a, const uint32_t* b) {
    asm volatile(
        "mma.sync.aligned.m16n8k16.row.col.f32.f16.f16.f32 "
        "{%0,%1,%2,%3}, {%4,%5,%6,%7}, {%8,%9}, {%0,%1,%2,%3};"
        : "+f"(c[0]), "+f"(c[1]), "+f"(c[2]), "+f"(c[3])
        : "r"(a[0]), "r"(a[1]), "r"(a[2]), "r"(a[3]), "r"(b[0]), "r"(b[1]));
}
__device__ __forceinline__ uint32_t swz(uint32_t off) {
    return off ^ ((off >> 3) & 0x70);
}
__device__ __forceinline__ float gelu_exact(float v) {
    return 0.5f * v * (1.f + erff(v * 0.70710678118654752440f));
}

// ---------------- small kernels --------------------------------------------
__global__ void zero_cnt_kernel() {
    if (threadIdx.x < EE) g_cnt[threadIdx.x] = 0;
}

__global__ __launch_bounds__(256) void convert_x_kernel(const float* __restrict__ x) {
    size_t i = ((size_t)blockIdx.x * 256 + threadIdx.x) * 4;
    float4 v = *(const float4*)(x + i);
    __half2 p0 = __floats2half2_rn(v.x, v.y);
    __half2 p1 = __floats2half2_rn(v.z, v.w);
    uint2 o; o.x = *(uint32_t*)&p0; o.y = *(uint32_t*)&p1;
    *(uint2*)(g_x16 + i) = o;
}

// which=0: w1 [E][D][H] -> [E][H][D]; which=1: w2 [E][H][D] -> [E][D][H]
__global__ __launch_bounds__(256) void transpose_split_kernel(
    const float* __restrict__ in, int which)
{
    int R = which ? HH : DD;
    int C = which ? DD : HH;
    __half* outp = which ? g_w2t : g_w1t;
    __shared__ float tile[32][33];
    int e  = blockIdx.z;
    int r0 = blockIdx.y * 32, c0 = blockIdx.x * 32;
    const float* src = in + (size_t)e * R * C;
    for (int i = threadIdx.y; i < 32; i += 8)
        tile[i][threadIdx.x] = src[(size_t)(r0 + i) * C + c0 + threadIdx.x];
    __syncthreads();
    __half* dst = outp + (size_t)e * R * C;
    for (int i = threadIdx.y; i < 32; i += 8) {
        float v = tile[threadIdx.x][i];
        dst[(size_t)(c0 + i) * R + r0 + threadIdx.x] = __float2half_rn(v);
    }
}

__global__ __launch_bounds__(256) void router_kernel(
    const float* __restrict__ x,
    const float* __restrict__ rw,
    const float* __restrict__ rb)
{
    int gwarp = (blockIdx.x * blockDim.x + threadIdx.x) >> 5;
    int lane  = threadIdx.x & 31;
    if (gwarp >= TT) return;
    const float* xr = x + (size_t)gwarp * DD;

    float acc[EE];
#pragma unroll
    for (int e = 0; e < EE; e++) acc[e] = 0.f;
    for (int d = lane; d < DD; d += 32) {
        float xv = xr[d];
        const float4 w0 = *(const float4*)(rw + (size_t)d * EE);
        const float4 w1 = *(const float4*)(rw + (size_t)d * EE + 4);
        acc[0] += xv * w0.x; acc[1] += xv * w0.y;
        acc[2] += xv * w0.z; acc[3] += xv * w0.w;
        acc[4] += xv * w1.x; acc[5] += xv * w1.y;
        acc[6] += xv * w1.z; acc[7] += xv * w1.w;
    }
#pragma unroll
    for (int off = 16; off; off >>= 1)
#pragma unroll
        for (int e = 0; e < EE; e++)
            acc[e] += __shfl_down_sync(0xffffffffu, acc[e], off);
    if (lane == 0) {
        float lg[EE];
#pragma unroll
        for (int e = 0; e < EE; e++) lg[e] = acc[e] + rb[e];
        int i0 = 0; float v0 = lg[0];
#pragma unroll
        for (int e = 1; e < EE; e++) if (lg[e] > v0) { v0 = lg[e]; i0 = e; }
        int i1 = -1; float v1 = -3.4e38f;
#pragma unroll
        for (int e = 0; e < EE; e++) {
            if (e == i0) continue;
            if (lg[e] > v1) { v1 = lg[e]; i1 = e; }
        }
        float e1 = __expf(v1 - v0);
        float w0 = 1.f / (1.f + e1);
        float w1 = e1 * w0;
        int s0 = atomicAdd(&g_cnt[i0], 1);
        g_tok[i0 * TT + s0] = gwarp; g_wt[i0 * TT + s0] = w0; g_kidx[i0 * TT + s0] = 0;
        int s1 = atomicAdd(&g_cnt[i1], 1);
        g_tok[i1 * TT + s1] = gwarp; g_wt[i1 * TT + s1] = w1; g_kidx[i1 * TT + s1] = 1;
    }
}

// ---------------- fp16 GEMM via mma.sync (tensor pipe) ----------------------
// D[m,n] = sum_k A[m,k]*B[n,k]. CTA: 128m x 256n, 512 thr = 16 warps (4m x 4n),
// warp tile 32x64. K-chunk 64, SW128 K-major smem, 4-stage cp.async,
// single __syncthreads per chunk.
template<int K_TOT, bool G1>
__global__ void __launch_bounds__(512, 1) gemm_tc_kernel(const float* __restrict__ bias)
{
    constexpr int NK    = K_TOT / 64;
    constexpr int AB    = 128 * 128;           // A bytes/stage (16 KB)
    constexpr int BB    = 256 * 128;           // B bytes/stage (32 KB)
    constexpr int STAGE = AB + BB;             // 48 KB
    constexpr int NTOT  = G1 ? HH : DD;

    int e   = blockIdx.z;
    int cnt = g_cnt[e];
    int m0  = blockIdx.y * 128;
    if (m0 >= cnt) return;
    int n0  = blockIdx.x * 256;

    extern __shared__ char dynsm[];
    uint32_t dsm = (smem_u32(dynsm) + 1023u) & ~1023u;

    int tid = threadIdx.x, wid = tid >> 5, lane = tid & 31;
    int warp_m = (wid & 3) * 32;
    int warp_n = (wid >> 2) * 64;

    // A loads: 128 rows x 8 chunks of 16B; thread t -> row t>>2, chunks 2*(t&3)+{0,1}
    int a_lrow = tid >> 2;
    int a_lseg = (tid & 3) * 2;
    const __half* arow;
    if (G1) {
        int gr = m0 + a_lrow; if (gr > cnt - 1) gr = cnt - 1;
        arow = g_x16 + (size_t)g_tok[e * TT + gr] * DD;
    } else {
        arow = g_h16 + ((size_t)e * HPAD + m0 + a_lrow) * HH;
    }
    // B loads: 256 rows x 8 chunks; thread t -> row t>>1, chunks 4*(t&1)+{0..3}
    int b_lrow = tid >> 1;
    int b_lseg = (tid & 1) * 4;
    const __half* brow = (G1 ? g_w1t : g_w2t) +
        ((size_t)e * NTOT + n0 + b_lrow) * (size_t)K_TOT;

    auto load_stage = [&](int s, int k0) {
        uint32_t st = dsm + s * STAGE;
#pragma unroll
        for (int q = 0; q < 2; q++) {
            int seg = a_lseg + q;
            cpa16(st + swz((uint32_t)(a_lrow * 128 + seg * 16)), arow + k0 + seg * 8);
        }
#pragma unroll
        for (int q = 0; q < 4; q++) {
            int seg = b_lseg + q;
            cpa16(st + AB + swz((uint32_t)(b_lrow * 128 + seg * 16)), brow + k0 + seg * 8);
        }
        cpa_commit();
    };

    float acc[2][8][4];
#pragma unroll
    for (int i = 0; i < 2; i++)
#pragma unroll
        for (int j = 0; j < 8; j++)
#pragma unroll
            for (int q = 0; q < 4; q++) acc[i][j][q] = 0.f;

    int a_r  = (lane & 7) + ((lane >> 3) & 1) * 8;
    int a_c  = (lane >> 4) * 16;
    int b_r  = (lane & 7) + (lane >> 4) * 8;
    int b_c  = ((lane >> 3) & 1) * 16;

    load_stage(0, 0);
    load_stage(1, 64);
    load_stage(2, 128);

    for (int i = 0; i < NK; i++) {
        if (i < NK - 2)       cpa_wait<2>();
        else if (i == NK - 2) cpa_wait<1>();
        else                  cpa_wait<0>();
        __syncthreads();
        if (i + 3 < NK) load_stage((i + 3) & 3, (i + 3) * 64);

        uint32_t st = dsm + (i & 3) * STAGE;
#pragma unroll
        for (int kk = 0; kk < 4; kk++) {
            int c0 = kk * 32;
            uint32_t A[2][4], B[8][2];
#pragma unroll
            for (int mf = 0; mf < 2; mf++) {
                int row = warp_m + mf * 16 + a_r;
                ldsm4(A[mf], st + swz((uint32_t)(row * 128 + c0 + a_c)));
            }
#pragma unroll
            for (int np = 0; np < 4; np++) {
                int row = warp_n + np * 16 + b_r;
                uint32_t r4[4];
                ldsm4(r4, st + AB + swz((uint32_t)(row * 128 + c0 + b_c)));
                B[2 * np][0] = r4[0]; B[2 * np][1] = r4[1];
                B[2 * np + 1][0] = r4[2]; B[2 * np + 1][1] = r4[3];
            }
#pragma unroll
            for (int mf = 0; mf < 2; mf++)
#pragma unroll
                for (int nf = 0; nf < 8; nf++)
                    mma16816(acc[mf][nf], A[mf], B[nf]);
        }
    }

    // ---------------- epilogue ----------------
    int lane4 = lane >> 2;
    int lcol  = (lane & 3) * 2;

#pragma unroll
    for (int mf = 0; mf < 2; mf++) {
#pragma unroll
        for (int h = 0; h < 2; h++) {
            int gr = m0 + warp_m + mf * 16 + h * 8 + lane4;
            if (gr >= cnt) continue;
            if (G1) {
                __half* oh = g_h16 + ((size_t)e * HPAD + gr) * HH;
                const float* bp = bias + (size_t)e * NTOT;
#pragma unroll
                for (int nf = 0; nf < 8; nf++) {
                    int n = n0 + warp_n + nf * 8 + lcol;
                    float v0 = gelu_exact(acc[mf][nf][h * 2 + 0] + bp[n]);
                    float v1 = gelu_exact(acc[mf][nf][h * 2 + 1] + bp[n + 1]);
                    __half2 hp = __floats2half2_rn(v0, v1);
                    *(uint32_t*)&oh[n] = *(uint32_t*)&hp;
                }
            } else {
                int idx = e * TT + gr;
                int   tok = g_tok[idx];
                float wt  = g_wt[idx];
                int   kx  = g_kidx[idx];
                float* orow = g_yp + ((size_t)tok * 2 + kx) * DD;
                const float* bp = bias + (size_t)e * NTOT;
#pragma unroll
                for (int nf = 0; nf < 8; nf++) {
                    int n = n0 + warp_n + nf * 8 + lcol;
                    float2 o;
                    o.x = (acc[mf][nf][h * 2 + 0] + bp[n])     * wt;
                    o.y = (acc[mf][nf][h * 2 + 1] + bp[n + 1]) * wt;
                    *(float2*)(orow + n) = o;
                }
            }
        }
    }
}

// ---------------- residual + LayerNorm --------------------------------------
__device__ __forceinline__ float block_sum256(float v) {
    __shared__ float sh[8];
    int lane = threadIdx.x & 31, w = threadIdx.x >> 5;
#pragma unroll
    for (int o = 16; o; o >>= 1) v += __shfl_down_sync(0xffffffffu, v, o);
    if (lane == 0) sh[w] = v;
    __syncthreads();
    if (threadIdx.x == 0) {
        float s = 0.f;
#pragma unroll
        for (int i = 0; i < 8; i++) s += sh[i];
        sh[0] = s;
    }
    __syncthreads();
    float r = sh[0];
    __syncthreads();
    return r;
}

__global__ __launch_bounds__(256) void ln_kernel(
    const float* __restrict__ x,
    const float* __restrict__ gamma,
    const float* __restrict__ beta,
    float* __restrict__ out)
{
    int t = blockIdx.x;
    const float* xr = x + (size_t)t * DD;
    const float* p0 = g_yp + (size_t)t * 2 * DD;
    const float* p1 = p0 + DD;

    float v[3];
    float s = 0.f;
#pragma unroll
    for (int i = 0; i < 3; i++) {
        int d = threadIdx.x + i * 256;
        v[i] = xr[d] + p0[d] + p1[d];
        s += v[i];
    }
    s = block_sum256(s);
    float mu = s * (1.f / (float)DD);
    float q = 0.f;
#pragma unroll
    for (int i = 0; i < 3; i++) { float dl = v[i] - mu; q += dl * dl; }
    q = block_sum256(q);
    float rstd = rsqrtf(q * (1.f / (float)DD) + 1e-5f);
#pragma unroll
    for (int i = 0; i < 3; i++) {
        int d = threadIdx.x + i * 256;
        out[(size_t)t * DD + d] = (v[i] - mu) * rstd * gamma[d] + beta[d];
    }
}

// ---------------------------------------------------------------------------
extern "C" void kernel_launch(void* const* d_in, const int* in_sizes, int n_in,
                              void* d_out, int out_size)
{
    (void)in_sizes; (void)n_in; (void)out_size;
    const float* x   = (const float*)d_in[0];
    const float* rw  = (const float*)d_in[1];
    const float* rb  = (const float*)d_in[2];
    const float* w1  = (const float*)d_in[3];
    const float* b1  = (const float*)d_in[4];
    const float* w2  = (const float*)d_in[5];
    const float* b2  = (const float*)d_in[6];
    const float* gam = (const float*)d_in[7];
    const float* bet = (const float*)d_in[8];
    float* out = (float*)d_out;

    const int SMEM_SZ = 4 * (128 + 256) * 128 + 1024;   // 4 stages x 48KB + pad
    cudaFuncSetAttribute(gemm_tc_kernel<DD, true>,
                         cudaFuncAttributeMaxDynamicSharedMemorySize, SMEM_SZ);
    cudaFuncSetAttribute(gemm_tc_kernel<HH, false>,
                         cudaFuncAttributeMaxDynamicSharedMemorySize, SMEM_SZ);

    zero_cnt_kernel<<<1, 32>>>();
    router_kernel<<<TT / 8, 256>>>(x, rw, rb);
    convert_x_kernel<<<(TT * DD) / (256 * 4), 256>>>(x);
    transpose_split_kernel<<<dim3(HH / 32, DD / 32, EE), dim3(32, 8)>>>(w1, 0);
    transpose_split_kernel<<<dim3(DD / 32, HH / 32, EE), dim3(32, 8)>>>(w2, 1);
    gemm_tc_kernel<DD, true><<<dim3(HH / 256, TT / 128, EE), 512, SMEM_SZ>>>(b1);
    gemm_tc_kernel<HH, false><<<dim3(DD / 256, TT / 128, EE), 512, SMEM_SZ>>>(b2);
    ln_kernel<<<TT, 256>>>(x, gam, bet, out);
}

// round 14
// speedup vs baseline: 1.1132x; 1.0045x over previous
#include <cuda_runtime.h>
#include <cuda_fp16.h>
#include <cstdint>

#define TT 16384
#define DD 768
#define HH 3072
#define EE 8
#define HPAD (TT + 128)

// ---------------- scratch globals ------------------------------------------
__device__ int   g_cnt[EE];
__device__ int   g_tok[EE * TT];
__device__ float g_wt [EE * TT];
__device__ int   g_kidx[EE * TT];
__device__ __half g_x16[(size_t)TT * DD];
__device__ __half g_w1t[(size_t)EE * HH * DD];  // [E][H][D] K-major
__device__ __half g_w2t[(size_t)EE * DD * HH];  // [E][D][H] K-major
__device__ __half g_h16[(size_t)EE * HPAD * HH];
__device__ float g_yp[(size_t)TT * 2 * DD];

// ---------------- PTX helpers (base ISA only) -------------------------------
__device__ __forceinline__ uint32_t smem_u32(const void* p) {
    uint32_t a;
    asm("{ .reg .u64 t; cvta.to.shared.u64 t, %1; cvt.u32.u64 %0, t; }"
        : "=r"(a) : "l"(p));
    return a;
}
__device__ __forceinline__ void cpa16(uint32_t dst, const void* src) {
    asm volatile("cp.async.cg.shared.global [%0], [%1], 16;" :: "r"(dst), "l"(src));
}
__device__ __forceinline__ void cpa_commit() {
    asm volatile("cp.async.commit_group;" ::: "memory");
}
template<int N> __device__ __forceinline__ void cpa_wait() {
    asm volatile("cp.async.wait_group %0;" :: "n"(N) : "memory");
}
__device__ __forceinline__ void ldsm4(uint32_t* r, uint32_t addr) {
    asm volatile("ldmatrix.sync.aligned.m8n8.x4.shared.b16 {%0,%1,%2,%3}, [%4];"
                 : "=r"(r[0]), "=r"(r[1]), "=r"(r[2]), "=r"(r[3]) : "r"(addr));
}
__device__ __forceinline__ void mma16816(float* c, const uint32_t* a, const uint32_t* b) {
    asm volatile(
        "mma.sync.aligned.m16n8k16.row.col.f32.f16.f16.f32 "
        "{%0,%1,%2,%3}, {%4,%5,%6,%7}, {%8,%9}, {%0,%1,%2,%3};"
        : "+f"(c[0]), "+f"(c[1]), "+f"(c[2]), "+f"(c[3])
        : "r"(a[0]), "r"(a[1]), "r"(a[2]), "r"(a[3]), "r"(b[0]), "r"(b[1]));
}
__device__ __forceinline__ uint32_t swz(uint32_t off) {
    return off ^ ((off >> 3) & 0x70);
}
__device__ __forceinline__ float gelu_exact(float v) {
    return 0.5f * v * (1.f + erff(v * 0.70710678118654752440f));
}

// ---------------- small kernels --------------------------------------------
__global__ void zero_cnt_kernel() {
    if (threadIdx.x < EE) g_cnt[threadIdx.x] = 0;
}

// Transpose+convert: in [E][R][C] fp32 -> global (selected INSIDE kernel)
// [E][C][R] fp16. which=0: w1 (R=DD,C=HH) -> g_w1t. which=1: w2 (R=HH,C=DD) -> g_w2t.
// 64(r) x 32(c) tile; loads 128B coalesced, stores __half2 (128B per warp).
__global__ __launch_bounds__(256) void transpose_cvt_kernel(
    const float* __restrict__ in, int which)
{
    const int R = which ? HH : DD;
    const int C = which ? DD : HH;
    __half* outp = which ? g_w2t : g_w1t;   // device-side symbol ref (legal)

    __shared__ float tile[32][65];          // [c][r-part]
    int e  = blockIdx.z;
    int r0 = blockIdx.y * 64, c0 = blockIdx.x * 32;
    const float* src = in + (size_t)e * R * C;
    int tx = threadIdx.x & 31, ty = threadIdx.x >> 5;
    for (int i = ty; i < 64; i += 8)
        tile[tx][i] = src[(size_t)(r0 + i) * C + c0 + tx];
    __syncthreads();
    __half* dst = outp + (size_t)e * R * C;
    for (int i = ty; i < 32; i += 8) {
        __half2 v = __floats2half2_rn(tile[i][2 * tx], tile[i][2 * tx + 1]);
        *(__half2*)(dst + (size_t)(c0 + i) * R + r0 + 2 * tx) = v;
    }
}

// Router with fused x -> fp16 conversion (one warp per token).
__global__ __launch_bounds__(256) void router_kernel(
    const float* __restrict__ x,
    const float* __restrict__ rw,
    const float* __restrict__ rb)
{
    int gwarp = (blockIdx.x * blockDim.x + threadIdx.x) >> 5;
    int lane  = threadIdx.x & 31;
    if (gwarp >= TT) return;
    const float* xr = x + (size_t)gwarp * DD;
    __half* xo = g_x16 + (size_t)gwarp * DD;

    float acc[EE];
#pragma unroll
    for (int e = 0; e < EE; e++) acc[e] = 0.f;
    for (int d = lane; d < DD; d += 32) {
        float xv = xr[d];
        xo[d] = __float2half_rn(xv);
        const float4 w0 = *(const float4*)(rw + (size_t)d * EE);
        const float4 w1 = *(const float4*)(rw + (size_t)d * EE + 4);
        acc[0] += xv * w0.x; acc[1] += xv * w0.y;
        acc[2] += xv * w0.z; acc[3] += xv * w0.w;
        acc[4] += xv * w1.x; acc[5] += xv * w1.y;
        acc[6] += xv * w1.z; acc[7] += xv * w1.w;
    }
#pragma unroll
    for (int off = 16; off; off >>= 1)
#pragma unroll
        for (int e = 0; e < EE; e++)
            acc[e] += __shfl_down_sync(0xffffffffu, acc[e], off);
    if (lane == 0) {
        float lg[EE];
#pragma unroll
        for (int e = 0; e < EE; e++) lg[e] = acc[e] + rb[e];
        int i0 = 0; float v0 = lg[0];
#pragma unroll
        for (int e = 1; e < EE; e++) if (lg[e] > v0) { v0 = lg[e]; i0 = e; }
        int i1 = -1; float v1 = -3.4e38f;
#pragma unroll
        for (int e = 0; e < EE; e++) {
            if (e == i0) continue;
            if (lg[e] > v1) { v1 = lg[e]; i1 = e; }
        }
        float e1 = __expf(v1 - v0);
        float w0 = 1.f / (1.f + e1);
        float w1 = e1 * w0;
        int s0 = atomicAdd(&g_cnt[i0], 1);
        g_tok[i0 * TT + s0] = gwarp; g_wt[i0 * TT + s0] = w0; g_kidx[i0 * TT + s0] = 0;
        int s1 = atomicAdd(&g_cnt[i1], 1);
        g_tok[i1 * TT + s1] = gwarp; g_wt[i1 * TT + s1] = w1; g_kidx[i1 * TT + s1] = 1;
    }
}

// ---------------- fp16 GEMM via mma.sync (tensor pipe) ----------------------
// D[m,n] = sum_k A[m,k]*B[n,k]. CTA: 128m x 256n, 512 thr = 16 warps (4m x 4n),
// warp tile 32x64. K-chunk 64, SW128 K-major smem, 4-stage cp.async,
// single __syncthreads per chunk.  (Identical to the R10 passing version.)
template<int K_TOT, bool G1>
__global__ void __launch_bounds__(512, 1) gemm_tc_kernel(const float* __restrict__ bias)
{
    constexpr int NK    = K_TOT / 64;
    constexpr int AB    = 128 * 128;           // A bytes/stage (16 KB)
    constexpr int BB    = 256 * 128;           // B bytes/stage (32 KB)
    constexpr int STAGE = AB + BB;             // 48 KB
    constexpr int NTOT  = G1 ? HH : DD;

    int e   = blockIdx.z;
    int cnt = g_cnt[e];
    int m0  = blockIdx.y * 128;
    if (m0 >= cnt) return;
    int n0  = blockIdx.x * 256;

    extern __shared__ char dynsm[];
    uint32_t dsm = (smem_u32(dynsm) + 1023u) & ~1023u;

    int tid = threadIdx.x, wid = tid >> 5, lane = tid & 31;
    int warp_m = (wid & 3) * 32;
    int warp_n = (wid >> 2) * 64;

    // A loads: 128 rows x 8 chunks of 16B; thread t -> row t>>2, chunks 2*(t&3)+{0,1}
    int a_lrow = tid >> 2;
    int a_lseg = (tid & 3) * 2;
    const __half* arow;
    if (G1) {
        int gr = m0 + a_lrow; if (gr > cnt - 1) gr = cnt - 1;
        arow = g_x16 + (size_t)g_tok[e * TT + gr] * DD;
    } else {
        arow = g_h16 + ((size_t)e * HPAD + m0 + a_lrow) * HH;
    }
    // B loads: 256 rows x 8 chunks; thread t -> row t>>1, chunks 4*(t&1)+{0..3}
    int b_lrow = tid >> 1;
    int b_lseg = (tid & 1) * 4;
    const __half* brow = (G1 ? g_w1t : g_w2t) +
        ((size_t)e * NTOT + n0 + b_lrow) * (size_t)K_TOT;

    auto load_stage = [&](int s, int k0) {
        uint32_t st = dsm + s * STAGE;
#pragma unroll
        for (int q = 0; q < 2; q++) {
            int seg = a_lseg + q;
            cpa16(st + swz((uint32_t)(a_lrow * 128 + seg * 16)), arow + k0 + seg * 8);
        }
#pragma unroll
        for (int q = 0; q < 4; q++) {
            int seg = b_lseg + q;
            cpa16(st + AB + swz((uint32_t)(b_lrow * 128 + seg * 16)), brow + k0 + seg * 8);
        }
        cpa_commit();
    };

    float acc[2][8][4];
#pragma unroll
    for (int i = 0; i < 2; i++)
#pragma unroll
        for (int j = 0; j < 8; j++)
#pragma unroll
            for (int q = 0; q < 4; q++) acc[i][j][q] = 0.f;

    int a_r  = (lane & 7) + ((lane >> 3) & 1) * 8;
    int a_c  = (lane >> 4) * 16;
    int b_r  = (lane & 7) + (lane >> 4) * 8;
    int b_c  = ((lane >> 3) & 1) * 16;

    load_stage(0, 0);
    load_stage(1, 64);
    load_stage(2, 128);

    for (int i = 0; i < NK; i++) {
        if (i < NK - 2)       cpa_wait<2>();
        else if (i == NK - 2) cpa_wait<1>();
        else                  cpa_wait<0>();
        __syncthreads();
        if (i + 3 < NK) load_stage((i + 3) & 3, (i + 3) * 64);

        uint32_t st = dsm + (i & 3) * STAGE;
#pragma unroll
        for (int kk = 0; kk < 4; kk++) {
            int c0 = kk * 32;
            uint32_t A[2][4], B[8][2];
#pragma unroll
            for (int mf = 0; mf < 2; mf++) {
                int row = warp_m + mf * 16 + a_r;
                ldsm4(A[mf], st + swz((uint32_t)(row * 128 + c0 + a_c)));
            }
#pragma unroll
            for (int np = 0; np < 4; np++) {
                int row = warp_n + np * 16 + b_r;
                uint32_t r4[4];
                ldsm4(r4, st + AB + swz((uint32_t)(row * 128 + c0 + b_c)));
                B[2 * np][0] = r4[0]; B[2 * np][1] = r4[1];
                B[2 * np + 1][0] = r4[2]; B[2 * np + 1][1] = r4[3];
            }
#pragma unroll
            for (int mf = 0; mf < 2; mf++)
#pragma unroll
                for (int nf = 0; nf < 8; nf++)
                    mma16816(acc[mf][nf], A[mf], B[nf]);
        }
    }

    // ---------------- epilogue ----------------
    int lane4 = lane >> 2;
    int lcol  = (lane & 3) * 2;

#pragma unroll
    for (int mf = 0; mf < 2; mf++) {
#pragma unroll
        for (int h = 0; h < 2; h++) {
            int gr = m0 + warp_m + mf * 16 + h * 8 + lane4;
            if (gr >= cnt) continue;
            if (G1) {
                __half* oh = g_h16 + ((size_t)e * HPAD + gr) * HH;
                const float* bp = bias + (size_t)e * NTOT;
#pragma unroll
                for (int nf = 0; nf < 8; nf++) {
                    int n = n0 + warp_n + nf * 8 + lcol;
                    float v0 = gelu_exact(acc[mf][nf][h * 2 + 0] + bp[n]);
                    float v1 = gelu_exact(acc[mf][nf][h * 2 + 1] + bp[n + 1]);
                    __half2 hp = __floats2half2_rn(v0, v1);
                    *(uint32_t*)&oh[n] = *(uint32_t*)&hp;
                }
            } else {
                int idx = e * TT + gr;
                int   tok = g_tok[idx];
                float wt  = g_wt[idx];
                int   kx  = g_kidx[idx];
                float* orow = g_yp + ((size_t)tok * 2 + kx) * DD;
                const float* bp = bias + (size_t)e * NTOT;
#pragma unroll
                for (int nf = 0; nf < 8; nf++) {
                    int n = n0 + warp_n + nf * 8 + lcol;
                    float2 o;
                    o.x = (acc[mf][nf][h * 2 + 0] + bp[n])     * wt;
                    o.y = (acc[mf][nf][h * 2 + 1] + bp[n + 1]) * wt;
                    *(float2*)(orow + n) = o;
                }
            }
        }
    }
}

// ---------------- residual + LayerNorm --------------------------------------
__device__ __forceinline__ float block_sum256(float v) {
    __shared__ float sh[8];
    int lane = threadIdx.x & 31, w = threadIdx.x >> 5;
#pragma unroll
    for (int o = 16; o; o >>= 1) v += __shfl_down_sync(0xffffffffu, v, o);
    if (lane == 0) sh[w] = v;
    __syncthreads();
    if (threadIdx.x == 0) {
        float s = 0.f;
#pragma unroll
        for (int i = 0; i < 8; i++) s += sh[i];
        sh[0] = s;
    }
    __syncthreads();
    float r = sh[0];
    __syncthreads();
    return r;
}

__global__ __launch_bounds__(256) void ln_kernel(
    const float* __restrict__ x,
    const float* __restrict__ gamma,
    const float* __restrict__ beta,
    float* __restrict__ out)
{
    int t = blockIdx.x;
    const float* xr = x + (size_t)t * DD;
    const float* p0 = g_yp + (size_t)t * 2 * DD;
    const float* p1 = p0 + DD;

    float v[3];
    float s = 0.f;
#pragma unroll
    for (int i = 0; i < 3; i++) {
        int d = threadIdx.x + i * 256;
        v[i] = xr[d] + p0[d] + p1[d];
        s += v[i];
    }
    s = block_sum256(s);
    float mu = s * (1.f / (float)DD);
    float q = 0.f;
#pragma unroll
    for (int i = 0; i < 3; i++) { float dl = v[i] - mu; q += dl * dl; }
    q = block_sum256(q);
    float rstd = rsqrtf(q * (1.f / (float)DD) + 1e-5f);
#pragma unroll
    for (int i = 0; i < 3; i++) {
        int d = threadIdx.x + i * 256;
        out[(size_t)t * DD + d] = (v[i] - mu) * rstd * gamma[d] + beta[d];
    }
}

// ---------------------------------------------------------------------------
extern "C" void kernel_launch(void* const* d_in, const int* in_sizes, int n_in,
                              void* d_out, int out_size)
{
    (void)in_sizes; (void)n_in; (void)out_size;
    const float* x   = (const float*)d_in[0];
    const float* rw  = (const float*)d_in[1];
    const float* rb  = (const float*)d_in[2];
    const float* w1  = (const float*)d_in[3];
    const float* b1  = (const float*)d_in[4];
    const float* w2  = (const float*)d_in[5];
    const float* b2  = (const float*)d_in[6];
    const float* gam = (const float*)d_in[7];
    const float* bet = (const float*)d_in[8];
    float* out = (float*)d_out;

    const int SMEM_SZ = 4 * (128 + 256) * 128 + 1024;   // 4 stages x 48KB + pad
    cudaFuncSetAttribute(gemm_tc_kernel<DD, true>,
                         cudaFuncAttributeMaxDynamicSharedMemorySize, SMEM_SZ);
    cudaFuncSetAttribute(gemm_tc_kernel<HH, false>,
                         cudaFuncAttributeMaxDynamicSharedMemorySize, SMEM_SZ);

    zero_cnt_kernel<<<1, 32>>>();
    router_kernel<<<TT / 8, 256>>>(x, rw, rb);
    // w1 [E][DD][HH] -> g_w1t [E][HH][DD]
    transpose_cvt_kernel<<<dim3(HH / 32, DD / 64, EE), 256>>>(w1, 0);
    // w2 [E][HH][DD] -> g_w2t [E][DD][HH]
    transpose_cvt_kernel<<<dim3(DD / 32, HH / 64, EE), 256>>>(w2, 1);
    gemm_tc_kernel<DD, true><<<dim3(HH / 256, TT / 128, EE), 512, SMEM_SZ>>>(b1);
    gemm_tc_kernel<HH, false><<<dim3(DD / 256, TT / 128, EE), 512, SMEM_SZ>>>(b2);
    ln_kernel<<<TT, 256>>>(x, gam, bet, out);
}

// round 17
// speedup vs baseline: 1.1575x; 1.0398x over previous
#include <cuda_runtime.h>
#include <cuda_fp16.h>
#include <cstdint>

#define TT 16384
#define DD 768
#define HH 3072
#define EE 8
#define HPAD (TT + 128)

// ---------------- scratch globals ------------------------------------------
__device__ int   g_cnt[EE];
__device__ int   g_tok[EE * TT];
__device__ float g_wt [EE * TT];
__device__ int   g_kidx[EE * TT];
__device__ __half g_x16[(size_t)TT * DD];
__device__ __half g_w1t[(size_t)EE * HH * DD];  // [E][H][D] K-major
__device__ __half g_w2t[(size_t)EE * DD * HH];  // [E][D][H] K-major
__device__ __half g_h16[(size_t)EE * HPAD * HH];
__device__ __half g_yp16[(size_t)TT * 2 * DD];  // fp16 weighted partials

// ---------------- PTX helpers (base ISA only) -------------------------------
__device__ __forceinline__ uint32_t smem_u32(const void* p) {
    uint32_t a;
    asm("{ .reg .u64 t; cvta.to.shared.u64 t, %1; cvt.u32.u64 %0, t; }"
        : "=r"(a) : "l"(p));
    return a;
}
__device__ __forceinline__ void cpa16(uint32_t dst, const void* src) {
    asm volatile("cp.async.cg.shared.global [%0], [%1], 16;" :: "r"(dst), "l"(src));
}
__device__ __forceinline__ void cpa_commit() {
    asm volatile("cp.async.commit_group;" ::: "memory");
}
template<int N> __device__ __forceinline__ void cpa_wait() {
    asm volatile("cp.async.wait_group %0;" :: "n"(N) : "memory");
}
__device__ __forceinline__ void ldsm4(uint32_t* r, uint32_t addr) {
    asm volatile("ldmatrix.sync.aligned.m8n8.x4.shared.b16 {%0,%1,%2,%3}, [%4];"
                 : "=r"(r[0]), "=r"(r[1]), "=r"(r[2]), "=r"(r[3]) : "r"(addr));
}
__device__ __forceinline__ void mma16816(float* c, const uint32_t* a, const uint32_t* b) {
    asm volatile(
        "mma.sync.aligned.m16n8k16.row.col.f32.f16.f16.f32 "
        "{%0,%1,%2,%3}, {%4,%5,%6,%7}, {%8,%9}, {%0,%1,%2,%3};"
        : "+f"(c[0]), "+f"(c[1]), "+f"(c[2]), "+f"(c[3])
        : "r"(a[0]), "r"(a[1]), "r"(a[2]), "r"(a[3]), "r"(b[0]), "r"(b[1]));
}
__device__ __forceinline__ uint32_t swz(uint32_t off) {
    return off ^ ((off >> 3) & 0x70);
}
__device__ __forceinline__ float gelu_exact(float v) {
    return 0.5f * v * (1.f + erff(v * 0.70710678118654752440f));
}

// ---------------- small kernels --------------------------------------------
__global__ void zero_cnt_kernel() {
    if (threadIdx.x < EE) g_cnt[threadIdx.x] = 0;
}

// Transpose+convert: in [E][R][C] fp32 -> [E][C][R] fp16 (global chosen in-kernel).
// 64x64 tile, 256 threads. Global loads float4; smem stores SCALAR (alignment-safe);
// global stores uint2 (8B, aligned).
__global__ __launch_bounds__(256) void transpose_cvt_kernel(
    const float* __restrict__ in, int which)
{
    const int R = which ? HH : DD;
    const int C = which ? DD : HH;
    __half* outp = which ? g_w2t : g_w1t;   // device-side symbol ref

    __shared__ float tile[64][65];          // [r][c], +1 pad
    int e  = blockIdx.z;
    int r0 = blockIdx.y * 64, c0 = blockIdx.x * 64;
    const float* src = in + (size_t)e * R * C;
    int tx = threadIdx.x & 15;              // 16 col-groups of 4 floats
    int ty = threadIdx.x >> 4;              // 16 rows per pass

#pragma unroll
    for (int rr = 0; rr < 64; rr += 16) {
        float4 v = *(const float4*)(src + (size_t)(r0 + ty + rr) * C + c0 + tx * 4);
        tile[ty + rr][tx * 4 + 0] = v.x;
        tile[ty + rr][tx * 4 + 1] = v.y;
        tile[ty + rr][tx * 4 + 2] = v.z;
        tile[ty + rr][tx * 4 + 3] = v.w;
    }
    __syncthreads();

    __half* dst = outp + (size_t)e * R * C;
#pragma unroll
    for (int cc = 0; cc < 64; cc += 16) {
        int c = ty + cc;
        float f0 = tile[tx * 4 + 0][c];
        float f1 = tile[tx * 4 + 1][c];
        float f2 = tile[tx * 4 + 2][c];
        float f3 = tile[tx * 4 + 3][c];
        __half2 h0 = __floats2half2_rn(f0, f1);
        __half2 h1 = __floats2half2_rn(f2, f3);
        uint2 o; o.x = *(uint32_t*)&h0; o.y = *(uint32_t*)&h1;
        *(uint2*)(dst + (size_t)(c0 + c) * R + r0 + tx * 4) = o;
    }
}

// Router with fused x -> fp16 conversion (one warp per token).
__global__ __launch_bounds__(256) void router_kernel(
    const float* __restrict__ x,
    const float* __restrict__ rw,
    const float* __restrict__ rb)
{
    int gwarp = (blockIdx.x * blockDim.x + threadIdx.x) >> 5;
    int lane  = threadIdx.x & 31;
    if (gwarp >= TT) return;
    const float* xr = x + (size_t)gwarp * DD;
    __half* xo = g_x16 + (size_t)gwarp * DD;

    float acc[EE];
#pragma unroll
    for (int e = 0; e < EE; e++) acc[e] = 0.f;
    for (int d = lane; d < DD; d += 32) {
        float xv = xr[d];
        xo[d] = __float2half_rn(xv);
        const float4 w0 = *(const float4*)(rw + (size_t)d * EE);
        const float4 w1 = *(const float4*)(rw + (size_t)d * EE + 4);
        acc[0] += xv * w0.x; acc[1] += xv * w0.y;
        acc[2] += xv * w0.z; acc[3] += xv * w0.w;
        acc[4] += xv * w1.x; acc[5] += xv * w1.y;
        acc[6] += xv * w1.z; acc[7] += xv * w1.w;
    }
#pragma unroll
    for (int off = 16; off; off >>= 1)
#pragma unroll
        for (int e = 0; e < EE; e++)
            acc[e] += __shfl_down_sync(0xffffffffu, acc[e], off);
    if (lane == 0) {
        float lg[EE];
#pragma unroll
        for (int e = 0; e < EE; e++) lg[e] = acc[e] + rb[e];
        int i0 = 0; float v0 = lg[0];
#pragma unroll
        for (int e = 1; e < EE; e++) if (lg[e] > v0) { v0 = lg[e]; i0 = e; }
        int i1 = -1; float v1 = -3.4e38f;
#pragma unroll
        for (int e = 0; e < EE; e++) {
            if (e == i0) continue;
            if (lg[e] > v1) { v1 = lg[e]; i1 = e; }
        }
        float e1 = __expf(v1 - v0);
        float w0 = 1.f / (1.f + e1);
        float w1 = e1 * w0;
        int s0 = atomicAdd(&g_cnt[i0], 1);
        g_tok[i0 * TT + s0] = gwarp; g_wt[i0 * TT + s0] = w0; g_kidx[i0 * TT + s0] = 0;
        int s1 = atomicAdd(&g_cnt[i1], 1);
        g_tok[i1 * TT + s1] = gwarp; g_wt[i1 * TT + s1] = w1; g_kidx[i1 * TT + s1] = 1;
    }
}

// ---------------- fp16 GEMM via mma.sync (tensor pipe) ----------------------
// D[m,n] = sum_k A[m,k]*B[n,k]. CTA: 128m x 256n, 512 thr = 16 warps (4m x 4n),
// warp tile 32x64. K-chunk 64, SW128 K-major smem, 4-stage cp.async,
// single __syncthreads per chunk.
template<int K_TOT, bool G1>
__global__ void __launch_bounds__(512, 1) gemm_tc_kernel(const float* __restrict__ bias)
{
    constexpr int NK    = K_TOT / 64;
    constexpr int AB    = 128 * 128;           // A bytes/stage (16 KB)
    constexpr int BB    = 256 * 128;           // B bytes/stage (32 KB)
    constexpr int STAGE = AB + BB;             // 48 KB
    constexpr int NTOT  = G1 ? HH : DD;

    int e   = blockIdx.z;
    int cnt = g_cnt[e];
    int m0  = blockIdx.y * 128;
    if (m0 >= cnt) return;
    int n0  = blockIdx.x * 256;

    extern __shared__ char dynsm[];
    uint32_t dsm = (smem_u32(dynsm) + 1023u) & ~1023u;

    int tid = threadIdx.x, wid = tid >> 5, lane = tid & 31;
    int warp_m = (wid & 3) * 32;
    int warp_n = (wid >> 2) * 64;

    int a_lrow = tid >> 2;
    int a_lseg = (tid & 3) * 2;
    const __half* arow;
    if (G1) {
        int gr = m0 + a_lrow; if (gr > cnt - 1) gr = cnt - 1;
        arow = g_x16 + (size_t)g_tok[e * TT + gr] * DD;
    } else {
        arow = g_h16 + ((size_t)e * HPAD + m0 + a_lrow) * HH;
    }
    int b_lrow = tid >> 1;
    int b_lseg = (tid & 1) * 4;
    const __half* brow = (G1 ? g_w1t : g_w2t) +
        ((size_t)e * NTOT + n0 + b_lrow) * (size_t)K_TOT;

    auto load_stage = [&](int s, int k0) {
        uint32_t st = dsm + s * STAGE;
#pragma unroll
        for (int q = 0; q < 2; q++) {
            int seg = a_lseg + q;
            cpa16(st + swz((uint32_t)(a_lrow * 128 + seg * 16)), arow + k0 + seg * 8);
        }
#pragma unroll
        for (int q = 0; q < 4; q++) {
            int seg = b_lseg + q;
            cpa16(st + AB + swz((uint32_t)(b_lrow * 128 + seg * 16)), brow + k0 + seg * 8);
        }
        cpa_commit();
    };

    float acc[2][8][4];
#pragma unroll
    for (int i = 0; i < 2; i++)
#pragma unroll
        for (int j = 0; j < 8; j++)
#pragma unroll
            for (int q = 0; q < 4; q++) acc[i][j][q] = 0.f;

    int a_r  = (lane & 7) + ((lane >> 3) & 1) * 8;
    int a_c  = (lane >> 4) * 16;
    int b_r  = (lane & 7) + (lane >> 4) * 8;
    int b_c  = ((lane >> 3) & 1) * 16;

    load_stage(0, 0);
    load_stage(1, 64);
    load_stage(2, 128);

    for (int i = 0; i < NK; i++) {
        if (i < NK - 2)       cpa_wait<2>();
        else if (i == NK - 2) cpa_wait<1>();
        else                  cpa_wait<0>();
        __syncthreads();
        if (i + 3 < NK) load_stage((i + 3) & 3, (i + 3) * 64);

        uint32_t st = dsm + (i & 3) * STAGE;
#pragma unroll
        for (int kk = 0; kk < 4; kk++) {
            int c0 = kk * 32;
            uint32_t A[2][4], B[8][2];
#pragma unroll
            for (int mf = 0; mf < 2; mf++) {
                int row = warp_m + mf * 16 + a_r;
                ldsm4(A[mf], st + swz((uint32_t)(row * 128 + c0 + a_c)));
            }
#pragma unroll
            for (int np = 0; np < 4; np++) {
                int row = warp_n + np * 16 + b_r;
                uint32_t r4[4];
                ldsm4(r4, st + AB + swz((uint32_t)(row * 128 + c0 + b_c)));
                B[2 * np][0] = r4[0]; B[2 * np][1] = r4[1];
                B[2 * np + 1][0] = r4[2]; B[2 * np + 1][1] = r4[3];
            }
#pragma unroll
            for (int mf = 0; mf < 2; mf++)
#pragma unroll
                for (int nf = 0; nf < 8; nf++)
                    mma16816(acc[mf][nf], A[mf], B[nf]);
        }
    }

    // ---------------- epilogue ----------------
    int lane4 = lane >> 2;
    int lcol  = (lane & 3) * 2;

#pragma unroll
    for (int mf = 0; mf < 2; mf++) {
#pragma unroll
        for (int h = 0; h < 2; h++) {
            int gr = m0 + warp_m + mf * 16 + h * 8 + lane4;
            if (gr >= cnt) continue;
            if (G1) {
                __half* oh = g_h16 + ((size_t)e * HPAD + gr) * HH;
                const float* bp = bias + (size_t)e * NTOT;
#pragma unroll
                for (int nf = 0; nf < 8; nf++) {
                    int n = n0 + warp_n + nf * 8 + lcol;
                    float v0 = gelu_exact(acc[mf][nf][h * 2 + 0] + bp[n]);
                    float v1 = gelu_exact(acc[mf][nf][h * 2 + 1] + bp[n + 1]);
                    __half2 hp = __floats2half2_rn(v0, v1);
                    *(uint32_t*)&oh[n] = *(uint32_t*)&hp;
                }
            } else {
                int idx = e * TT + gr;
                int   tok = g_tok[idx];
                float wt  = g_wt[idx];
                int   kx  = g_kidx[idx];
                __half* orow = g_yp16 + ((size_t)tok * 2 + kx) * DD;
                const float* bp = bias + (size_t)e * NTOT;
#pragma unroll
                for (int nf = 0; nf < 8; nf++) {
                    int n = n0 + warp_n + nf * 8 + lcol;
                    float o0 = (acc[mf][nf][h * 2 + 0] + bp[n])     * wt;
                    float o1 = (acc[mf][nf][h * 2 + 1] + bp[n + 1]) * wt;
                    __half2 hp = __floats2half2_rn(o0, o1);
                    *(uint32_t*)&orow[n] = *(uint32_t*)&hp;
                }
            }
        }
    }
}

// ---------------- residual + LayerNorm --------------------------------------
__device__ __forceinline__ float block_sum256(float v) {
    __shared__ float sh[8];
    int lane = threadIdx.x & 31, w = threadIdx.x >> 5;
#pragma unroll
    for (int o = 16; o; o >>= 1) v += __shfl_down_sync(0xffffffffu, v, o);
    if (lane == 0) sh[w] = v;
    __syncthreads();
    if (threadIdx.x == 0) {
        float s = 0.f;
#pragma unroll
        for (int i = 0; i < 8; i++) s += sh[i];
        sh[0] = s;
    }
    __syncthreads();
    float r = sh[0];
    __syncthreads();
    return r;
}

__global__ __launch_bounds__(256) void ln_kernel(
    const float* __restrict__ x,
    const float* __restrict__ gamma,
    const float* __restrict__ beta,
    float* __restrict__ out)
{
    int t = blockIdx.x;
    const float* xr = x + (size_t)t * DD;
    const __half* p0 = g_yp16 + (size_t)t * 2 * DD;
    const __half* p1 = p0 + DD;

    float v[3];
    float s = 0.f;
#pragma unroll
    for (int i = 0; i < 3; i++) {
        int d = threadIdx.x + i * 256;
        v[i] = xr[d] + __half2float(p0[d]) + __half2float(p1[d]);
        s += v[i];
    }
    s = block_sum256(s);
    float mu = s * (1.f / (float)DD);
    float q = 0.f;
#pragma unroll
    for (int i = 0; i < 3; i++) { float dl = v[i] - mu; q += dl * dl; }
    q = block_sum256(q);
    float rstd = rsqrtf(q * (1.f / (float)DD) + 1e-5f);
#pragma unroll
    for (int i = 0; i < 3; i++) {
        int d = threadIdx.x + i * 256;
        out[(size_t)t * DD + d] = (v[i] - mu) * rstd * gamma[d] + beta[d];
    }
}

// ---------------------------------------------------------------------------
extern "C" void kernel_launch(void* const* d_in, const int* in_sizes, int n_in,
                              void* d_out, int out_size)
{
    (void)in_sizes; (void)n_in; (void)out_size;
    const float* x   = (const float*)d_in[0];
    const float* rw  = (const float*)d_in[1];
    const float* rb  = (const float*)d_in[2];
    const float* w1  = (const float*)d_in[3];
    const float* b1  = (const float*)d_in[4];
    const float* w2  = (const float*)d_in[5];
    const float* b2  = (const float*)d_in[6];
    const float* gam = (const float*)d_in[7];
    const float* bet = (const float*)d_in[8];
    float* out = (float*)d_out;

    const int SMEM_SZ = 4 * (128 + 256) * 128 + 1024;   // 4 stages x 48KB + pad
    cudaFuncSetAttribute(gemm_tc_kernel<DD, true>,
                         cudaFuncAttributeMaxDynamicSharedMemorySize, SMEM_SZ);
    cudaFuncSetAttribute(gemm_tc_kernel<HH, false>,
                         cudaFuncAttributeMaxDynamicSharedMemorySize, SMEM_SZ);

    zero_cnt_kernel<<<1, 32>>>();
    router_kernel<<<TT / 8, 256>>>(x, rw, rb);
    // w1 [E][DD][HH] -> g_w1t [E][HH][DD]:  R=DD, C=HH
    transpose_cvt_kernel<<<dim3(HH / 64, DD / 64, EE), 256>>>(w1, 0);
    // w2 [E][HH][DD] -> g_w2t [E][DD][HH]:  R=HH, C=DD
    transpose_cvt_kernel<<<dim3(DD / 64, HH / 64, EE), 256>>>(w2, 1);
    gemm_tc_kernel<DD, true><<<dim3(HH / 256, TT / 128, EE), 512, SMEM_SZ>>>(b1);
    gemm_tc_kernel<HH, false><<<dim3(DD / 256, TT / 128, EE), 512, SMEM_SZ>>>(b2);
    ln_kernel<<<TT, 256>>>(x, gam, bet, out);
}